// round 16
// baseline (speedup 1.0000x reference)
#include <cuda_runtime.h>
#include <math.h>

#define AHW    43264          // 208*208
#define Q4     10816          // AHW/4
#define NB4    54080          // 5*Q4 conf float4s
#define WGRID  208
#define NCLS   80
#define SHIFT  17
#define HB     16384          // buckets over p4 float bits >> 17
#define CAP    2048
#define KTOP   1024
#define GRIDA  53
#define GRIDC  148
#define SLICE  366            // ceil(NB4/GRIDC)
#define GRIDB  32
#define GRIDN  128            // matrix blocks: 8 rows each

__device__ __align__(16) unsigned g_hist[HB];
__device__ unsigned            g_T;
__device__ unsigned long long  g_keys[CAP];
__device__ int                 g_count;
__device__ unsigned            g_sync0;
__device__ float4              g_tb[KTOP];
__device__ float               g_tconf[KTOP];
__device__ int                 g_tcls[KTOP];
__device__ unsigned            g_rowAny[32];
__device__ unsigned            g_sup[KTOP * 32];

extern __shared__ unsigned char dynsmem[];

// ================================================================ K1: smem-privatized histogram + last-block threshold
__global__ void __launch_bounds__(1024) hist_kernel(const float* __restrict__ x) {
    unsigned* sh = (unsigned*)dynsmem;           // 64 KB private histogram
    __shared__ unsigned wsum[32];
    __shared__ bool s_last;
    int tid  = threadIdx.x;
    int wid  = tid >> 5;
    int lane = tid & 31;
    int bid  = blockIdx.x;
    int t    = bid * 1024 + tid;

    // zero private hist
    uint4* s4 = (uint4*)sh;
#pragma unroll
    for (int i = 0; i < 4; i++) s4[tid + i * 1024] = make_uint4(0u, 0u, 0u, 0u);
    __syncthreads();

    if (t < NB4) {
        int a = t / Q4;
        int q = t - a * Q4;
        float4 p = __ldg((const float4*)(x + (size_t)(a * 85 + 4) * AHW) + q);
        if (p.x > 0.f) atomicAdd(&sh[__float_as_uint(p.x) >> SHIFT], 1u);
        if (p.y > 0.f) atomicAdd(&sh[__float_as_uint(p.y) >> SHIFT], 1u);
        if (p.z > 0.f) atomicAdd(&sh[__float_as_uint(p.z) >> SHIFT], 1u);
        if (p.w > 0.f) atomicAdd(&sh[__float_as_uint(p.w) >> SHIFT], 1u);
    }
    // zero per-replay scratch on spare lanes
    if (bid == 0) { g_tconf[tid] = 0.f; g_tcls[tid] = 0; }
    if (bid == 1) g_tb[tid] = make_float4(0.f, 0.f, 0.f, 0.f);
    if (bid == 2 && tid < 32) g_rowAny[tid] = 0u;
    __syncthreads();

    // merge: only non-zero buckets hit global atomics (<=53 ops per address chip-wide)
#pragma unroll
    for (int i = 0; i < 16; i++) {
        unsigned v = sh[tid + i * 1024];
        if (v) atomicAdd(&g_hist[tid + i * 1024], v);
    }

    // last-block handoff
    __threadfence();
    __syncthreads();
    if (tid == 0) s_last = (atomicAdd(&g_sync0, 1u) == GRIDA - 1);
    __syncthreads();
    if (!s_last) return;
    __threadfence();

    // threshold: 16 buckets per thread in regs; zero g_hist in place
    const uint4* h4 = (const uint4*)g_hist;
    uint4 a0 = h4[tid * 4 + 0], a1 = h4[tid * 4 + 1];
    uint4 a2 = h4[tid * 4 + 2], a3 = h4[tid * 4 + 3];
    uint4 z = make_uint4(0u, 0u, 0u, 0u);
    ((uint4*)g_hist)[tid * 4 + 0] = z;
    ((uint4*)g_hist)[tid * 4 + 1] = z;
    ((uint4*)g_hist)[tid * 4 + 2] = z;
    ((uint4*)g_hist)[tid * 4 + 3] = z;
    unsigned chunk = a0.x + a0.y + a0.z + a0.w + a1.x + a1.y + a1.z + a1.w
                   + a2.x + a2.y + a2.z + a2.w + a3.x + a3.y + a3.z + a3.w;
    unsigned s = chunk;
#pragma unroll
    for (int d = 1; d < 32; d <<= 1) {
        unsigned v = __shfl_down_sync(0xffffffffu, s, d);
        if (lane + d < 32) s += v;
    }
    if (tid == 0) g_T = 0u;
    if (lane == 0) wsum[wid] = s;
    __syncthreads();
    if (wid == 0) {
        unsigned w = wsum[lane];
        unsigned t2 = w;
#pragma unroll
        for (int d = 1; d < 32; d <<= 1) {
            unsigned v = __shfl_down_sync(0xffffffffu, t2, d);
            if (lane + d < 32) t2 += v;
        }
        wsum[lane] = t2 - w;                    // exclusive suffix of warp totals
    }
    __syncthreads();
    unsigned suf = s + wsum[wid];
    unsigned sufNext = suf - chunk;
    if (suf >= KTOP && sufNext < KTOP) {        // unique cutoff-owning thread
        unsigned bv[16] = {a0.x, a0.y, a0.z, a0.w, a1.x, a1.y, a1.z, a1.w,
                           a2.x, a2.y, a2.z, a2.w, a3.x, a3.y, a3.z, a3.w};
        unsigned acc = sufNext;
        int T = tid * 16;
#pragma unroll
        for (int b = 15; b >= 0; b--) {
            acc += bv[b];
            if (acc >= KTOP) { T = tid * 16 + b; break; }
        }
        T -= 2;                                 // tie-safety margin
        if (T < 0) T = 0;
        g_T = (unsigned)T;
    }
}

// ================================================================ K2: distributed compact + fp64 keys
__global__ void __launch_bounds__(384) compact_kernel(const float* __restrict__ x) {
    int tid = threadIdx.x;
    if (tid >= SLICE) return;
    int i = blockIdx.x * SLICE + tid;
    if (i >= NB4) return;
    unsigned T = g_T;
    int a = i / Q4;
    int q = i - a * Q4;
    float4 p = __ldg((const float4*)(x + (size_t)(a * 85 + 4) * AHW) + q);
    float pv[4] = {p.x, p.y, p.z, p.w};
#pragma unroll
    for (int c = 0; c < 4; c++) {
        float v = pv[c];
        if (v > 0.f && (__float_as_uint(v) >> SHIFT) >= T) {
            int pos = atomicAdd(&g_count, 1);
            if (pos < CAP) {
                unsigned idx = (unsigned)(a * AHW + q * 4 + c);
                double e = exp(-(double)v);
                float conf = (float)(1.0 / (1.0 + e));
                g_keys[pos] = ((unsigned long long)__float_as_uint(conf) << 32)
                              | (unsigned)(~idx);
            }
        }
    }
}

// ================================================================ K3: rank-by-counting + in-block gather-decode
__global__ void __launch_bounds__(1024) rankemit_kernel(const float* __restrict__ x,
                                                        const float* __restrict__ anchors) {
    __shared__ unsigned long long kc[CAP];
    __shared__ int rkk[64];
    int tid  = threadIdx.x;
    int wid  = tid >> 5;
    int lane = tid & 31;
    int bid  = blockIdx.x;

    kc[tid]        = g_keys[tid];
    kc[tid + 1024] = g_keys[tid + 1024];
    __syncthreads();

    // ---- rank phase: 16 threads per candidate
    {
        int cl  = tid >> 4;
        int seg = tid & 15;
        unsigned long long my = kc[bid * 64 + cl];
        int rk = 0;
#pragma unroll 8
        for (int it = 0; it < 128; it++)
            rk += (kc[it * 16 + seg] > my) ? 1 : 0;
#pragma unroll
        for (int off = 8; off > 0; off >>= 1)
            rk += __shfl_down_sync(0xffffffffu, rk, off, 16);
        if (seg == 0) rkk[cl] = (my != 0ull && rk < KTOP) ? rk : -1;
    }
    __syncthreads();

    // ---- decode phase: warp per candidate, 2 rounds
#pragma unroll
    for (int round = 0; round < 2; round++) {
        int c  = wid + round * 32;
        int rk = rkk[c];
        if (rk >= 0) {
            unsigned long long key = kc[bid * 64 + c];
            unsigned idx = ~(unsigned)(key & 0xFFFFFFFFull);
            float conf = __uint_as_float((unsigned)(key >> 32));
            int aa = idx / AHW;
            int s  = idx - aa * AHW;
            const float* px = x + (size_t)(aa * 85) * AHW + s;
            const float* pc = px + 5 * (size_t)AHW;
            float bv = -3.4e38f; int bi = NCLS;
#pragma unroll
            for (int mm = 0; mm < 3; mm++) {
                int k = lane + 32 * mm;
                if (k < NCLS) {
                    float v = __ldg(pc + (size_t)k * AHW);
                    if (v > bv || (v == bv && k < bi)) { bv = v; bi = k; }
                }
            }
#pragma unroll
            for (int off = 16; off > 0; off >>= 1) {
                float ov = __shfl_xor_sync(0xffffffffu, bv, off);
                int   oi = __shfl_xor_sync(0xffffffffu, bi, off);
                if (ov > bv || (ov == bv && oi < bi)) { bv = ov; bi = oi; }
            }
            if (lane == 0) {
                int h = s / WGRID;
                int w = s - h * WGRID;
                float p0 = __ldg(px);
                float p1 = __ldg(px + AHW);
                float p2 = __ldg(px + 2 * (size_t)AHW);
                float p3 = __ldg(px + 3 * (size_t)AHW);
                float aw = __ldg(&anchors[aa * 2]);
                float ah = __ldg(&anchors[aa * 2 + 1]);
                float bx = (1.f / (1.f + expf(-p0)) + (float)w) * 32.f;
                float by = (1.f / (1.f + expf(-p1)) + (float)h) * 32.f;
                g_tb[rk]    = make_float4(bx, by, expf(p2) * aw * 32.f, expf(p3) * ah * 32.f);
                g_tcls[rk]  = bi;
                g_tconf[rk] = conf;
            }
        }
    }
}

// ================================================================ K4: suppression matrix (128 blocks x 8 rows), slim smem
__global__ void __launch_bounds__(1024) matrix_kernel() {
    __shared__ float4 sb[KTOP];       // 16 KB static
    __shared__ int    scl[KTOP];      // 4 KB static
    __shared__ unsigned s_any8[8];

    int tid  = threadIdx.x;
    int wid  = tid >> 5;
    int lane = tid & 31;
    int bid  = blockIdx.x;

    // cleanup for next replay on spare capacity
    if (bid == 0) g_keys[tid] = 0ull;
    if (bid == 1) g_keys[tid + 1024] = 0ull;
    if (bid == 2 && tid == 0) { g_count = 0; g_sync0 = 0u; }

    sb[tid]  = __ldcg((const float4*)&g_tb[tid]);
    scl[tid] = __ldcg(&g_tcls[tid]);
    if (tid < 8) s_any8[tid] = 0u;
    __syncthreads();

    {
        int rloc = wid >> 2;                   // 0..7
        int jseg = wid & 3;                    // 0..3
        int i    = bid * 8 + rloc;
        float4 bi = sb[i];
        int   cli = scl[i];
        float x1min = (bi.x - bi.z) * 0.5f, y1min = (bi.y - bi.w) * 0.5f;
        float x1max = (bi.x + bi.z) * 0.5f, y1max = (bi.y + bi.w) * 0.5f;
        float a1 = fabsf((x1max - x1min) * (y1max - y1min));

        unsigned anyw = 0u;
#pragma unroll
        for (int c = 0; c < 8; c++) {
            int jw = jseg * 8 + c;
            int jj = jw * 32 + lane;
            float4 bj = sb[jj];
            bool sup = false;
            if (jj > i && scl[jj] == cli) {
                float x2min = (bj.x - bj.z) * 0.5f, y2min = (bj.y - bj.w) * 0.5f;
                float x2max = (bj.x + bj.z) * 0.5f, y2max = (bj.y + bj.w) * 0.5f;
                float iw = fmaxf(fminf(x1max, x2max) - fmaxf(x1min, x2min), 0.f);
                float ih = fmaxf(fminf(y1max, y2max) - fmaxf(y1min, y2min), 0.f);
                float inter = iw * ih;
                float a2 = fabsf((x2max - x2min) * (y2max - y2min));
                float iou = inter / (a1 + a2 - inter + 1e-6f);
                sup = (iou >= 0.5f);
            }
            unsigned wmask = __ballot_sync(0xffffffffu, sup);
            if (lane == 0) g_sup[i * 32 + jw] = wmask;
            anyw |= wmask;
        }
        if (lane == 0 && anyw) atomicOr(&s_any8[rloc], 1u);
    }
    __syncthreads();
    if (tid < 8 && s_any8[tid]) {
        int i = bid * 8 + tid;
        atomicOr(&g_rowAny[i >> 5], 1u << (i & 31));
    }
}

// ================================================================ K5: sweep — single block, big smem carveout only here
// dyn layout: rows 128K | sb 16K | scl 4K | scf 4K
#define OFF_SB   131072
#define OFF_SCL  147456
#define OFF_SCF  151552
#define SMEM_SW  155648
__global__ void __launch_bounds__(1024) sweep_kernel(float* __restrict__ out) {
    unsigned* rows = (unsigned*)dynsmem;
    float4*   sb   = (float4*)(dynsmem + OFF_SB);
    int*      scl  = (int*)(dynsmem + OFF_SCL);
    float*    scf  = (float*)(dynsmem + OFF_SCF);
    __shared__ unsigned s_keep[32];
    __shared__ unsigned s_init[32];
    __shared__ unsigned s_any[32];

    int tid  = threadIdx.x;
    int wid  = tid >> 5;
    int lane = tid & 31;

    sb[tid]  = g_tb[tid];
    scl[tid] = g_tcls[tid];
    float cf = g_tconf[tid];
    scf[tid] = cf;
    {
        unsigned vm = __ballot_sync(0xffffffffu, cf > 0.f);   // valid <=> conf > 0.5
        if (lane == 0) s_init[wid] = vm;
    }
    if (tid < 32) s_any[tid] = g_rowAny[tid];
    __syncthreads();
    for (int i = wid; i < KTOP; i += 32) {
        if ((s_any[i >> 5] >> (i & 31)) & 1u)
            rows[i * 32 + lane] = g_sup[i * 32 + lane];
    }
    __syncthreads();

    // greedy sweep (chain per event = LDS + ALU)
    if (tid < 32) {
        unsigned keepw = s_init[tid];
        unsigned anyv  = s_any[tid];
        for (int ww = 0; ww < 32; ww++) {
            unsigned aw  = __shfl_sync(0xffffffffu, anyv,  ww);
            unsigned cur = __shfl_sync(0xffffffffu, keepw, ww);
            unsigned act = cur & aw;
            while (act) {
                int b = __ffs(act) - 1;
                int i = ww * 32 + b;
                unsigned r_own = rows[i * 32 + tid];
                unsigned r_ww  = rows[i * 32 + ww];
                keepw &= ~r_own;
                cur   &= ~r_ww;
                act = cur & aw & (0xFFFFFFFEu << b);
            }
        }
        s_keep[tid] = keepw;
    }
    __syncthreads();

    bool k = (s_keep[tid >> 5] >> (tid & 31)) & 1u;
    float4 b  = sb[tid];
    int   cl  = scl[tid];
    float* o = out + (size_t)tid * 6;
    if (k) {
        o[0] = b.x; o[1] = b.y; o[2] = b.z; o[3] = b.w;
        o[4] = scf[tid]; o[5] = (float)cl;
    } else {
        o[0] = 0.f; o[1] = 0.f; o[2] = 0.f; o[3] = 0.f; o[4] = 0.f; o[5] = 0.f;
    }
}

// ---------------------------------------------------------------- launch
extern "C" void kernel_launch(void* const* d_in, const int* in_sizes, int n_in,
                              void* d_out, int out_size) {
    const float* x       = (const float*)d_in[0];
    const float* anchors = (const float*)d_in[1];
    float* out = (float*)d_out;

    static bool s_attr = false;
    if (!s_attr) {
        cudaFuncSetAttribute(hist_kernel, cudaFuncAttributeMaxDynamicSharedMemorySize, HB * 4);
        cudaFuncSetAttribute(sweep_kernel, cudaFuncAttributeMaxDynamicSharedMemorySize, SMEM_SW);
        s_attr = true;
    }

    hist_kernel<<<GRIDA, 1024, HB * 4>>>(x);
    compact_kernel<<<GRIDC, 384>>>(x);
    rankemit_kernel<<<GRIDB, 1024>>>(x, anchors);
    matrix_kernel<<<GRIDN, 1024>>>();
    sweep_kernel<<<1, 1024, SMEM_SW>>>(out);
}

// round 17
// speedup vs baseline: 1.3453x; 1.3453x over previous
#include <cuda_runtime.h>
#include <math.h>

#define AHW    43264          // 208*208
#define Q4     10816          // AHW/4
#define NB4    54080          // 5*Q4 conf float4s
#define WGRID  208
#define NCLS   80
#define SHIFT  18
#define HB     8192           // buckets over p4 float bits >> 18
#define CAP    2048
#define KTOP   1024
#define GRIDA  53
#define GRIDC  148
#define SLICE  366            // ceil(NB4/GRIDC)
#define GRIDR  128            // rankemit blocks (16 candidates each)
#define GRIDN  128            // matrix blocks: 8 rows each

__device__ __align__(16) unsigned g_hist[HB];
__device__ unsigned            g_T;
__device__ unsigned long long  g_keys[CAP];
__device__ int                 g_count;
__device__ unsigned            g_sync0, g_sync1;
__device__ float4              g_tb[KTOP];
__device__ float               g_tconf[KTOP];
__device__ int                 g_tcls[KTOP];
__device__ unsigned            g_rowAny[32];
__device__ unsigned            g_sup[KTOP * 32];

extern __shared__ unsigned char dynsmem[];

// ================================================================ K1: smem-privatized histogram + last-block threshold
__global__ void __launch_bounds__(1024) hist_kernel(const float* __restrict__ x) {
    unsigned* sh = (unsigned*)dynsmem;           // 32 KB private histogram
    __shared__ unsigned wsum[32];
    __shared__ bool s_last;
    int tid  = threadIdx.x;
    int wid  = tid >> 5;
    int lane = tid & 31;
    int bid  = blockIdx.x;
    int t    = bid * 1024 + tid;

    // zero private hist (8192 words = 2 uint4/thread)
    uint4* s4 = (uint4*)sh;
    s4[tid] = make_uint4(0u, 0u, 0u, 0u);
    s4[tid + 1024] = make_uint4(0u, 0u, 0u, 0u);
    __syncthreads();

    if (t < NB4) {
        int a = t / Q4;
        int q = t - a * Q4;
        float4 p = __ldg((const float4*)(x + (size_t)(a * 85 + 4) * AHW) + q);
        if (p.x > 0.f) atomicAdd(&sh[__float_as_uint(p.x) >> SHIFT], 1u);
        if (p.y > 0.f) atomicAdd(&sh[__float_as_uint(p.y) >> SHIFT], 1u);
        if (p.z > 0.f) atomicAdd(&sh[__float_as_uint(p.z) >> SHIFT], 1u);
        if (p.w > 0.f) atomicAdd(&sh[__float_as_uint(p.w) >> SHIFT], 1u);
    }
    // zero per-replay scratch on spare lanes
    if (bid == 0) { g_tconf[tid] = 0.f; g_tcls[tid] = 0; }
    if (bid == 1) g_tb[tid] = make_float4(0.f, 0.f, 0.f, 0.f);
    if (bid == 2 && tid < 32) g_rowAny[tid] = 0u;
    __syncthreads();

    // merge: only non-zero buckets hit global atomics (<=53 ops per address chip-wide)
#pragma unroll
    for (int i = 0; i < 8; i++) {
        unsigned v = sh[tid + i * 1024];
        if (v) atomicAdd(&g_hist[tid + i * 1024], v);
    }

    // last-block handoff
    __threadfence();
    __syncthreads();
    if (tid == 0) s_last = (atomicAdd(&g_sync0, 1u) == GRIDA - 1);
    __syncthreads();
    if (!s_last) return;
    __threadfence();

    // threshold: 8 buckets per thread in regs; zero g_hist in place
    const uint4* h4 = (const uint4*)g_hist;
    uint4 a0 = h4[tid * 2 + 0], a1 = h4[tid * 2 + 1];
    uint4 z = make_uint4(0u, 0u, 0u, 0u);
    ((uint4*)g_hist)[tid * 2 + 0] = z;
    ((uint4*)g_hist)[tid * 2 + 1] = z;
    unsigned chunk = a0.x + a0.y + a0.z + a0.w + a1.x + a1.y + a1.z + a1.w;
    unsigned s = chunk;
#pragma unroll
    for (int d = 1; d < 32; d <<= 1) {
        unsigned v = __shfl_down_sync(0xffffffffu, s, d);
        if (lane + d < 32) s += v;
    }
    if (tid == 0) g_T = 0u;
    if (lane == 0) wsum[wid] = s;
    __syncthreads();
    if (wid == 0) {
        unsigned w = wsum[lane];
        unsigned t2 = w;
#pragma unroll
        for (int d = 1; d < 32; d <<= 1) {
            unsigned v = __shfl_down_sync(0xffffffffu, t2, d);
            if (lane + d < 32) t2 += v;
        }
        wsum[lane] = t2 - w;                    // exclusive suffix of warp totals
    }
    __syncthreads();
    unsigned suf = s + wsum[wid];
    unsigned sufNext = suf - chunk;
    if (suf >= KTOP && sufNext < KTOP) {        // unique cutoff-owning thread
        unsigned bv[8] = {a0.x, a0.y, a0.z, a0.w, a1.x, a1.y, a1.z, a1.w};
        unsigned acc = sufNext;
        int T = tid * 8;
#pragma unroll
        for (int b = 7; b >= 0; b--) {
            acc += bv[b];
            if (acc >= KTOP) { T = tid * 8 + b; break; }
        }
        T -= 2;                                 // tie-safety margin
        if (T < 0) T = 0;
        g_T = (unsigned)T;
    }
}

// ================================================================ K2: distributed compact + fp64 keys
__global__ void __launch_bounds__(384) compact_kernel(const float* __restrict__ x) {
    int tid = threadIdx.x;
    if (tid >= SLICE) return;
    int i = blockIdx.x * SLICE + tid;
    if (i >= NB4) return;
    unsigned T = g_T;
    int a = i / Q4;
    int q = i - a * Q4;
    float4 p = __ldg((const float4*)(x + (size_t)(a * 85 + 4) * AHW) + q);
    float pv[4] = {p.x, p.y, p.z, p.w};
#pragma unroll
    for (int c = 0; c < 4; c++) {
        float v = pv[c];
        if (v > 0.f && (__float_as_uint(v) >> SHIFT) >= T) {
            int pos = atomicAdd(&g_count, 1);
            if (pos < CAP) {
                unsigned idx = (unsigned)(a * AHW + q * 4 + c);
                double e = exp(-(double)v);
                float conf = (float)(1.0 / (1.0 + e));
                g_keys[pos] = ((unsigned long long)__float_as_uint(conf) << 32)
                              | (unsigned)(~idx);
            }
        }
    }
}

// ================================================================ K3: rank-by-counting + gather-decode (128 blocks x 16 cand)
__global__ void __launch_bounds__(256) rankemit_kernel(const float* __restrict__ x,
                                                       const float* __restrict__ anchors) {
    __shared__ unsigned long long kc[CAP];
    __shared__ int rkk[16];
    int tid  = threadIdx.x;
    int wid  = tid >> 5;
    int lane = tid & 31;
    int bid  = blockIdx.x;

#pragma unroll
    for (int i = 0; i < 8; i++) kc[tid + i * 256] = g_keys[tid + i * 256];
    __syncthreads();

    // ---- rank phase: 16 threads per candidate (16 candidates)
    {
        int cl  = tid >> 4;                    // 0..15
        int seg = tid & 15;
        unsigned long long my = kc[bid * 16 + cl];
        int rk = 0;
#pragma unroll 8
        for (int it = 0; it < 128; it++)
            rk += (kc[it * 16 + seg] > my) ? 1 : 0;
#pragma unroll
        for (int off = 8; off > 0; off >>= 1)
            rk += __shfl_down_sync(0xffffffffu, rk, off, 16);
        if (seg == 0) rkk[cl] = (my != 0ull && rk < KTOP) ? rk : -1;
    }
    __syncthreads();

    // ---- decode phase: warp per candidate, 2 rounds (8 warps)
#pragma unroll
    for (int round = 0; round < 2; round++) {
        int c  = round * 8 + wid;              // 0..15
        int rk = rkk[c];
        if (rk >= 0) {
            unsigned long long key = kc[bid * 16 + c];
            unsigned idx = ~(unsigned)(key & 0xFFFFFFFFull);
            float conf = __uint_as_float((unsigned)(key >> 32));
            int aa = idx / AHW;
            int s  = idx - aa * AHW;
            const float* px = x + (size_t)(aa * 85) * AHW + s;
            const float* pc = px + 5 * (size_t)AHW;
            float bv = -3.4e38f; int bi = NCLS;
#pragma unroll
            for (int mm = 0; mm < 3; mm++) {
                int k = lane + 32 * mm;
                if (k < NCLS) {
                    float v = __ldg(pc + (size_t)k * AHW);
                    if (v > bv || (v == bv && k < bi)) { bv = v; bi = k; }
                }
            }
#pragma unroll
            for (int off = 16; off > 0; off >>= 1) {
                float ov = __shfl_xor_sync(0xffffffffu, bv, off);
                int   oi = __shfl_xor_sync(0xffffffffu, bi, off);
                if (ov > bv || (ov == bv && oi < bi)) { bv = ov; bi = oi; }
            }
            if (lane == 0) {
                int h = s / WGRID;
                int w = s - h * WGRID;
                float p0 = __ldg(px);
                float p1 = __ldg(px + AHW);
                float p2 = __ldg(px + 2 * (size_t)AHW);
                float p3 = __ldg(px + 3 * (size_t)AHW);
                float aw = __ldg(&anchors[aa * 2]);
                float ah = __ldg(&anchors[aa * 2 + 1]);
                float bx = (1.f / (1.f + expf(-p0)) + (float)w) * 32.f;
                float by = (1.f / (1.f + expf(-p1)) + (float)h) * 32.f;
                g_tb[rk]    = make_float4(bx, by, expf(p2) * aw * 32.f, expf(p3) * ah * 32.f);
                g_tcls[rk]  = bi;
                g_tconf[rk] = conf;
            }
        }
    }
}

// ================================================================ K4: matrix (128 blocks x 8 rows, slim smem) + last-block sweep
__global__ void __launch_bounds__(1024) nms_kernel(float* __restrict__ out) {
    __shared__ float4 sb[KTOP];       // 16 KB static
    __shared__ int    scl[KTOP];      // 4 KB
    __shared__ float  scf[KTOP];      // 4 KB
    __shared__ unsigned s_any8[8];
    __shared__ bool s_last;
    __shared__ unsigned s_keep[32];
    __shared__ unsigned s_init[32];
    __shared__ unsigned s_any[32];

    int tid  = threadIdx.x;
    int wid  = tid >> 5;
    int lane = tid & 31;
    int bid  = blockIdx.x;

    // cleanup for next replay on spare capacity
    if (bid == 0) g_keys[tid] = 0ull;
    if (bid == 1) g_keys[tid + 1024] = 0ull;
    if (bid == 2 && tid == 0) { g_count = 0; g_sync0 = 0u; }

    sb[tid]  = __ldcg((const float4*)&g_tb[tid]);
    scl[tid] = __ldcg(&g_tcls[tid]);
    scf[tid] = __ldcg(&g_tconf[tid]);
    if (tid < 8) s_any8[tid] = 0u;
    __syncthreads();

    // ---- matrix: 8 rows per block, 4 warps per row (8 j-words each)
    {
        int rloc = wid >> 2;                   // 0..7
        int jseg = wid & 3;                    // 0..3
        int i    = bid * 8 + rloc;
        float4 bi = sb[i];
        int   cli = scl[i];
        float x1min = (bi.x - bi.z) * 0.5f, y1min = (bi.y - bi.w) * 0.5f;
        float x1max = (bi.x + bi.z) * 0.5f, y1max = (bi.y + bi.w) * 0.5f;
        float a1 = fabsf((x1max - x1min) * (y1max - y1min));

        unsigned anyw = 0u;
#pragma unroll
        for (int c = 0; c < 8; c++) {
            int jw = jseg * 8 + c;
            int jj = jw * 32 + lane;
            float4 bj = sb[jj];
            bool sup = false;
            if (jj > i && scl[jj] == cli) {
                float x2min = (bj.x - bj.z) * 0.5f, y2min = (bj.y - bj.w) * 0.5f;
                float x2max = (bj.x + bj.z) * 0.5f, y2max = (bj.y + bj.w) * 0.5f;
                float iw = fmaxf(fminf(x1max, x2max) - fmaxf(x1min, x2min), 0.f);
                float ih = fmaxf(fminf(y1max, y2max) - fmaxf(y1min, y2min), 0.f);
                float inter = iw * ih;
                float a2 = fabsf((x2max - x2min) * (y2max - y2min));
                float iou = inter / (a1 + a2 - inter + 1e-6f);
                sup = (iou >= 0.5f);
            }
            unsigned wmask = __ballot_sync(0xffffffffu, sup);
            if (lane == 0) g_sup[i * 32 + jw] = wmask;
            anyw |= wmask;
        }
        if (lane == 0 && anyw) atomicOr(&s_any8[rloc], 1u);
    }
    __syncthreads();
    if (tid < 8 && s_any8[tid]) {
        int i = bid * 8 + tid;
        atomicOr(&g_rowAny[i >> 5], 1u << (i & 31));
    }

    // ---- last-block handoff
    __syncthreads();
    if (tid == 0) {
        __threadfence();
        s_last = (atomicAdd(&g_sync1, 1u) == GRIDN - 1);
    }
    __syncthreads();
    if (!s_last) return;
    __threadfence();

    // ---- sweep: few suppression events -> read g_sup rows directly from L2
    {
        unsigned vm = __ballot_sync(0xffffffffu, scf[tid] > 0.f);  // valid <=> conf > 0.5
        if (lane == 0) s_init[wid] = vm;
    }
    if (tid < 32) s_any[tid] = __ldcg(&g_rowAny[tid]);
    __syncthreads();

    if (tid < 32) {
        unsigned keepw = s_init[tid];
        unsigned anyv  = s_any[tid];
        for (int ww = 0; ww < 32; ww++) {
            unsigned aw  = __shfl_sync(0xffffffffu, anyv,  ww);
            unsigned cur = __shfl_sync(0xffffffffu, keepw, ww);
            unsigned act = cur & aw;
            while (act) {
                int b = __ffs(act) - 1;
                int i = ww * 32 + b;
                unsigned r_own = __ldcg(&g_sup[i * 32 + tid]);   // my word of row i
                unsigned r_ww  = __shfl_sync(0xffffffffu, r_own, ww);
                keepw &= ~r_own;
                cur   &= ~r_ww;
                act = cur & aw & (0xFFFFFFFEu << b);
            }
        }
        s_keep[tid] = keepw;
    }
    __syncthreads();

    {
        bool k = (s_keep[tid >> 5] >> (tid & 31)) & 1u;
        float4 b  = sb[tid];
        int   cl  = scl[tid];
        float* o = out + (size_t)tid * 6;
        if (k) {
            o[0] = b.x; o[1] = b.y; o[2] = b.z; o[3] = b.w;
            o[4] = scf[tid]; o[5] = (float)cl;
        } else {
            o[0] = 0.f; o[1] = 0.f; o[2] = 0.f; o[3] = 0.f; o[4] = 0.f; o[5] = 0.f;
        }
    }
    if (tid == 0) g_sync1 = 0u;
}

// ---------------------------------------------------------------- launch
extern "C" void kernel_launch(void* const* d_in, const int* in_sizes, int n_in,
                              void* d_out, int out_size) {
    const float* x       = (const float*)d_in[0];
    const float* anchors = (const float*)d_in[1];
    float* out = (float*)d_out;

    static bool s_attr = false;
    if (!s_attr) {
        cudaFuncSetAttribute(hist_kernel, cudaFuncAttributeMaxDynamicSharedMemorySize, HB * 4);
        s_attr = true;
    }

    hist_kernel<<<GRIDA, 1024, HB * 4>>>(x);
    compact_kernel<<<GRIDC, 384>>>(x);
    rankemit_kernel<<<GRIDR, 256>>>(x, anchors);
    nms_kernel<<<GRIDN, 1024>>>(out);
}